// round 1
// baseline (speedup 1.0000x reference)
#include <cuda_runtime.h>
#include <cuda_bf16.h>

#define BATCH 8
#define TE    256
#define TD    128
#define HE    512
#define HC    32           // h-chunk per smem tile

// ---------------- scratch (no allocations allowed) ----------------
__device__ float g_Ws[BATCH * TE * HE];   // 4 MB: enc @ W_a
__device__ float g_Uh[BATCH * TD * HE];   // 2 MB: dec @ U_a

__device__ __forceinline__ float fast_tanh(float x) {
    float y;
    asm("tanh.approx.f32 %0, %1;" : "=f"(y) : "f"(x));
    return y;
}

// ---------------- SGEMM: C[M,N] = A[M,K] @ B[K,N], all row-major ----------
#define BM 64
#define BN 64
#define BK 16
__global__ __launch_bounds__(256) void sgemm_Ws(const float* __restrict__ A,
                                                const float* __restrict__ Bm,
                                                int M, int N, int K, int which) {
    __shared__ float As[BK][BM + 1];
    __shared__ float Bs[BK][BN + 1];
    float* C = which == 0 ? g_Ws : g_Uh;

    const int tx = threadIdx.x;                 // 256 threads
    const int bm = blockIdx.y * BM, bn = blockIdx.x * BN;
    const int tm = (tx / 16) * 4, tn = (tx % 16) * 4;

    float acc[4][4] = {};
    for (int k0 = 0; k0 < K; k0 += BK) {
        #pragma unroll
        for (int i = tx; i < BM * BK; i += 256) {
            int m = i / BK, k = i % BK;
            As[k][m] = A[(bm + m) * K + k0 + k];
        }
        #pragma unroll
        for (int i = tx; i < BK * BN; i += 256) {
            int k = i / BN, n = i % BN;
            Bs[k][n] = Bm[(k0 + k) * N + bn + n];
        }
        __syncthreads();
        #pragma unroll
        for (int k = 0; k < BK; k++) {
            float a[4], b[4];
            #pragma unroll
            for (int i = 0; i < 4; i++) a[i] = As[k][tm + i];
            #pragma unroll
            for (int j = 0; j < 4; j++) b[j] = Bs[k][tn + j];
            #pragma unroll
            for (int i = 0; i < 4; i++)
                #pragma unroll
                for (int j = 0; j < 4; j++) acc[i][j] += a[i] * b[j];
        }
        __syncthreads();
    }
    #pragma unroll
    for (int i = 0; i < 4; i++)
        #pragma unroll
        for (int j = 0; j < 4; j++)
            C[(bm + tm + i) * N + bn + tn + j] = acc[i][j];
}

// ---------------- fused attention: one block per (b,d) ----------------
// e[t] = sum_h V[h]*tanh(Ws[b,t,h]+Uh[b,d,h]); softmax over t; c = e @ enc[b]
__global__ __launch_bounds__(256) void attn_kernel(const float* __restrict__ V,
                                                   const float* __restrict__ enc,
                                                   float* __restrict__ outC,
                                                   float* __restrict__ outE) {
    __shared__ float tile[TE][HC + 1];   // 33792 B, (t + h) % 32 banking: conflict-free
    __shared__ float sV[HE];
    __shared__ float sU[HE];
    __shared__ float sE[TE];
    __shared__ float red[8];

    const int tid = threadIdx.x;          // 256 threads, thread tid owns t = tid
    const int b = blockIdx.x >> 7;        // /TD
    const int d = blockIdx.x & (TD - 1);

    for (int i = tid; i < HE; i += 256) {
        sV[i] = V[i];
        sU[i] = g_Uh[(b * TD + d) * HE + i];
    }
    __syncthreads();

    const float* wsb = g_Ws + b * TE * HE;

    // ---------- e pass: MUFU-bound ----------
    float e_acc = 0.f;
    const int j  = tid & (HC - 1);        // 0..31, fixed per thread
    const int t0 = tid >> 5;              // 0..7
    for (int c = 0; c < HE / HC; c++) {
        const float u = sU[c * HC + j];   // loop-invariant: Uh add fused into load
        #pragma unroll
        for (int k = 0; k < TE / 8; k++) {
            int t = t0 + k * 8;
            tile[t][j] = wsb[t * HE + c * HC + j] + u;   // coalesced 128B per warp
        }
        __syncthreads();
        #pragma unroll
        for (int jj = 0; jj < HC; jj++) {
            float x = tile[tid][jj];                      // conflict-free
            e_acc += fast_tanh(x) * sV[c * HC + jj];      // broadcast LDS
        }
        __syncthreads();
    }

    // ---------- softmax over t (across the 256 threads) ----------
    float wm = e_acc;
    #pragma unroll
    for (int o = 16; o; o >>= 1) wm = fmaxf(wm, __shfl_xor_sync(0xffffffffu, wm, o));
    if ((tid & 31) == 0) red[tid >> 5] = wm;
    __syncthreads();
    float m = red[0];
    #pragma unroll
    for (int i = 1; i < 8; i++) m = fmaxf(m, red[i]);

    float p = __expf(e_acc - m);
    float ws = p;
    #pragma unroll
    for (int o = 16; o; o >>= 1) ws += __shfl_xor_sync(0xffffffffu, ws, o);
    __syncthreads();
    if ((tid & 31) == 0) red[tid >> 5] = ws;
    __syncthreads();
    float s = red[0];
    #pragma unroll
    for (int i = 1; i < 8; i++) s += red[i];

    float ef = p * (1.0f / s);
    sE[tid] = ef;
    outE[(b * TD + d) * TE + tid] = ef;
    __syncthreads();

    // ---------- context pass: c[h] = sum_t e[t]*enc[b,t,h] ----------
    const float2* enc2 = (const float2*)(enc + b * TE * HE);
    float2 acc = make_float2(0.f, 0.f);
    #pragma unroll 8
    for (int t = 0; t < TE; t++) {
        float e = sE[t];
        float2 v2 = enc2[t * (HE / 2) + tid];            // coalesced 256B per warp
        acc.x = fmaf(e, v2.x, acc.x);
        acc.y = fmaf(e, v2.y, acc.y);
    }
    ((float2*)(outC + (b * TD + d) * HE))[tid] = acc;
}

// ---------------- launch ----------------
extern "C" void kernel_launch(void* const* d_in, const int* in_sizes, int n_in,
                              void* d_out, int out_size) {
    const float* enc = (const float*)d_in[0];   // [8,256,512]
    const float* dec = (const float*)d_in[1];   // [8,128,512]
    const float* W_a = (const float*)d_in[2];   // [512,512]
    const float* U_a = (const float*)d_in[3];   // [512,512]
    const float* V_a = (const float*)d_in[4];   // [512,1]

    float* outC = (float*)d_out;                         // [8,128,512]
    float* outE = (float*)d_out + BATCH * TD * HE;       // [8,128,256]

    // Ws = enc @ W_a : M=2048, N=512, K=512
    sgemm_Ws<<<dim3(HE / BN, (BATCH * TE) / BM), 256>>>(enc, W_a, BATCH * TE, HE, HE, 0);
    // Uh = dec @ U_a : M=1024, N=512, K=512
    sgemm_Ws<<<dim3(HE / BN, (BATCH * TD) / BM), 256>>>(dec, U_a, BATCH * TD, HE, HE, 1);
    // fused attention
    attn_kernel<<<BATCH * TD, 256>>>(V_a, enc, outC, outE);
}

// round 2
// speedup vs baseline: 1.2563x; 1.2563x over previous
#include <cuda_runtime.h>
#include <cuda_bf16.h>

#define BATCH 8
#define TE    256
#define TD    128
#define HE    512
#define HC    16            // h-chunk per smem tile (keeps static smem < 48KB)
#define DT    8             // decoder steps per attn block

// ---------------- scratch (no allocations allowed) ----------------
__device__ float g_Ws[BATCH * TE * HE];   // 4 MB: enc @ W_a
__device__ float g_Uh[BATCH * TD * HE];   // 2 MB: dec @ U_a

__device__ __forceinline__ float fast_tanh(float x) {
    float y;
    asm("tanh.approx.f32 %0, %1;" : "=f"(y) : "f"(x));
    return y;
}

// ---------------- fused SGEMM: both projections in one launch ----------------
// C[M,N] = A[M,K] @ B[K,N] row-major. Row-tiles 0..31 -> Ws(enc@W), 32..47 -> Uh(dec@U).
#define BM 64
#define BN 64
#define BK 16
__global__ __launch_bounds__(128) void gemm_fused(const float* __restrict__ enc,
                                                  const float* __restrict__ dec,
                                                  const float* __restrict__ W,
                                                  const float* __restrict__ U) {
    __shared__ float As[BK][BM];    // [k][m]
    __shared__ float Bs[BK][BN];    // [k][n]

    const int tx = threadIdx.x;     // 128 threads
    const int rt = blockIdx.y;      // 0..47
    const float* A;  const float* B;  float* C;  int m0;
    if (rt < 32) { A = enc; B = W; C = g_Ws; m0 = rt * BM; }
    else         { A = dec; B = U; C = g_Uh; m0 = (rt - 32) * BM; }
    const int bn = blockIdx.x * BN;

    const int tm = (tx >> 4) * 8;   // 0..56
    const int tn = (tx & 15) * 4;   // 0..60

    float acc[8][4] = {};

    for (int k0 = 0; k0 < HE; k0 += BK) {
        // A tile: 64x16 floats = 256 float4, 2 per thread
        #pragma unroll
        for (int i = tx; i < (BM * BK) / 4; i += 128) {
            int row = i >> 2, q = i & 3;
            float4 a4 = *(const float4*)&A[(m0 + row) * HE + k0 + 4 * q];
            As[4 * q + 0][row] = a4.x;
            As[4 * q + 1][row] = a4.y;
            As[4 * q + 2][row] = a4.z;
            As[4 * q + 3][row] = a4.w;
        }
        // B tile: 16x64 floats = 256 float4, 2 per thread
        #pragma unroll
        for (int i = tx; i < (BK * BN) / 4; i += 128) {
            int k = i >> 4, nq = i & 15;
            *(float4*)&Bs[k][4 * nq] = *(const float4*)&B[(k0 + k) * HE + bn + 4 * nq];
        }
        __syncthreads();
        #pragma unroll
        for (int k = 0; k < BK; k++) {
            float4 a0 = *(const float4*)&As[k][tm];
            float4 a1 = *(const float4*)&As[k][tm + 4];
            float4 b0 = *(const float4*)&Bs[k][tn];
            float a[8] = {a0.x, a0.y, a0.z, a0.w, a1.x, a1.y, a1.z, a1.w};
            float b[4] = {b0.x, b0.y, b0.z, b0.w};
            #pragma unroll
            for (int i = 0; i < 8; i++)
                #pragma unroll
                for (int j = 0; j < 4; j++)
                    acc[i][j] = fmaf(a[i], b[j], acc[i][j]);
        }
        __syncthreads();
    }
    #pragma unroll
    for (int i = 0; i < 8; i++) {
        float4 o = make_float4(acc[i][0], acc[i][1], acc[i][2], acc[i][3]);
        *(float4*)&C[(m0 + tm + i) * HE + bn + tn] = o;
    }
}

// ---------------- fused attention: one block per (b, group of 8 d) ----------------
__global__ __launch_bounds__(256) void attn_kernel(const float* __restrict__ V,
                                                   const float* __restrict__ enc,
                                                   float* __restrict__ outC,
                                                   float* __restrict__ outE) {
    __shared__ float tile[TE][HC + 1];   // 17408 B, conflict-free reads (17 odd)
    __shared__ float sV[HE];             //  2 KB
    __shared__ float sU[DT * HE];        // 16 KB
    __shared__ float sE[DT * TE];        //  8 KB   (total 43.5 KB static)

    const int tid = threadIdx.x;          // 256 threads: thread tid owns t = tid
    const int b  = blockIdx.x >> 4;
    const int d0 = (blockIdx.x & 15) * DT;

    for (int i = tid; i < HE; i += 256) sV[i] = V[i];
    for (int i = tid; i < DT * HE; i += 256)
        sU[i] = g_Uh[(b * TD + d0) * HE + i];    // contiguous [8,512] slab
    __syncthreads();

    const float* wsb = g_Ws + b * TE * HE;

    // ---------- e pass: MUFU-bound, 8 d per tanh-tile pass ----------
    float e_acc[DT] = {};
    const int j  = tid & (HC - 1);        // 0..15
    const int t0 = tid >> 4;              // 0..15
    for (int c = 0; c < HE / HC; c++) {
        #pragma unroll
        for (int k = 0; k < TE / 16; k++) {
            int t = t0 + k * 16;
            tile[t][j] = wsb[t * HE + c * HC + j];    // coalesced
        }
        __syncthreads();
        #pragma unroll
        for (int jj = 0; jj < HC; jj++) {
            float x = tile[tid][jj];                   // conflict-free
            float v = sV[c * HC + jj];                 // broadcast
            #pragma unroll
            for (int d = 0; d < DT; d++)
                e_acc[d] += v * fast_tanh(x + sU[d * HE + c * HC + jj]);  // broadcast LDS
        }
        __syncthreads();
    }

    #pragma unroll
    for (int d = 0; d < DT; d++) sE[d * TE + tid] = e_acc[d];
    __syncthreads();

    // ---------- softmax: warp w handles d = w ----------
    {
        const int w = tid >> 5, lane = tid & 31;
        float vals[8];
        float m = -1e30f;
        #pragma unroll
        for (int i = 0; i < 8; i++) {
            vals[i] = sE[w * TE + lane + 32 * i];
            m = fmaxf(m, vals[i]);
        }
        #pragma unroll
        for (int o = 16; o; o >>= 1) m = fmaxf(m, __shfl_xor_sync(0xffffffffu, m, o));
        float s = 0.f;
        #pragma unroll
        for (int i = 0; i < 8; i++) {
            vals[i] = __expf(vals[i] - m);
            s += vals[i];
        }
        #pragma unroll
        for (int o = 16; o; o >>= 1) s += __shfl_xor_sync(0xffffffffu, s, o);
        float inv = 1.0f / s;
        float* oe = outE + (b * TD + d0 + w) * TE;
        #pragma unroll
        for (int i = 0; i < 8; i++) {
            float ef = vals[i] * inv;
            sE[w * TE + lane + 32 * i] = ef;
            oe[lane + 32 * i] = ef;
        }
    }
    __syncthreads();

    // ---------- context: c[d,h] = sum_t e[d,t]*enc[b,t,h], thread owns h-pair ----------
    const float2* enc2 = (const float2*)(enc + b * TE * HE);
    float2 acc[DT];
    #pragma unroll
    for (int d = 0; d < DT; d++) acc[d] = make_float2(0.f, 0.f);
    #pragma unroll 4
    for (int t = 0; t < TE; t++) {
        float2 v2 = enc2[t * (HE / 2) + tid];          // coalesced 256B/warp, L2-hit
        #pragma unroll
        for (int d = 0; d < DT; d++) {
            float e = sE[d * TE + t];                  // broadcast
            acc[d].x = fmaf(e, v2.x, acc[d].x);
            acc[d].y = fmaf(e, v2.y, acc[d].y);
        }
    }
    #pragma unroll
    for (int d = 0; d < DT; d++)
        ((float2*)(outC + (b * TD + d0 + d) * HE))[tid] = acc[d];
}

// ---------------- launch ----------------
extern "C" void kernel_launch(void* const* d_in, const int* in_sizes, int n_in,
                              void* d_out, int out_size) {
    const float* enc = (const float*)d_in[0];   // [8,256,512]
    const float* dec = (const float*)d_in[1];   // [8,128,512]
    const float* W_a = (const float*)d_in[2];   // [512,512]
    const float* U_a = (const float*)d_in[3];   // [512,512]
    const float* V_a = (const float*)d_in[4];   // [512,1]

    float* outC = (float*)d_out;                         // [8,128,512]
    float* outE = (float*)d_out + BATCH * TD * HE;       // [8,128,256]

    // Both projections: grid (N/64, 2048/64 + 1024/64) = (8, 48)
    gemm_fused<<<dim3(HE / BN, (BATCH * TE + BATCH * TD) / BM), 128>>>(enc, dec, W_a, U_a);
    // Fused attention: 128 blocks (8 b x 16 d-groups)
    attn_kernel<<<BATCH * (TD / DT), 256>>>(V_a, enc, outC, outE);
}

// round 3
// speedup vs baseline: 1.4303x; 1.1385x over previous
#include <cuda_runtime.h>
#include <cuda_bf16.h>

#define BATCH 8
#define TE    256
#define TD    128
#define HE    512
#define HC    16            // h-chunk per smem tile
#define DT    8             // decoder steps per e-pass block

// ---------------- scratch (no allocations allowed) ----------------
__device__ float g_Ws[BATCH * TE * HE];   // 4 MB: enc @ W_a
__device__ float g_Uh[BATCH * TD * HE];   // 2 MB: dec @ U_a

__device__ __forceinline__ float fast_tanh(float x) {
    float y;
    asm("tanh.approx.f32 %0, %1;" : "=f"(y) : "f"(x));
    return y;
}

// ---------------- fused SGEMM: both projections in one launch ----------------
#define BM 64
#define BN 64
#define BK 16
__global__ __launch_bounds__(128) void gemm_fused(const float* __restrict__ enc,
                                                  const float* __restrict__ dec,
                                                  const float* __restrict__ W,
                                                  const float* __restrict__ U) {
    __shared__ float As[BK][BM];
    __shared__ float Bs[BK][BN];

    const int tx = threadIdx.x;     // 128 threads
    const int rt = blockIdx.y;      // 0..47
    const float* A;  const float* B;  float* C;  int m0;
    if (rt < 32) { A = enc; B = W; C = g_Ws; m0 = rt * BM; }
    else         { A = dec; B = U; C = g_Uh; m0 = (rt - 32) * BM; }
    const int bn = blockIdx.x * BN;

    const int tm = (tx >> 4) * 8;
    const int tn = (tx & 15) * 4;

    float acc[8][4] = {};

    for (int k0 = 0; k0 < HE; k0 += BK) {
        #pragma unroll
        for (int i = tx; i < (BM * BK) / 4; i += 128) {
            int row = i >> 2, q = i & 3;
            float4 a4 = *(const float4*)&A[(m0 + row) * HE + k0 + 4 * q];
            As[4 * q + 0][row] = a4.x;
            As[4 * q + 1][row] = a4.y;
            As[4 * q + 2][row] = a4.z;
            As[4 * q + 3][row] = a4.w;
        }
        #pragma unroll
        for (int i = tx; i < (BK * BN) / 4; i += 128) {
            int k = i >> 4, nq = i & 15;
            *(float4*)&Bs[k][4 * nq] = *(const float4*)&B[(k0 + k) * HE + bn + 4 * nq];
        }
        __syncthreads();
        #pragma unroll
        for (int k = 0; k < BK; k++) {
            float4 a0 = *(const float4*)&As[k][tm];
            float4 a1 = *(const float4*)&As[k][tm + 4];
            float4 b0 = *(const float4*)&Bs[k][tn];
            float a[8] = {a0.x, a0.y, a0.z, a0.w, a1.x, a1.y, a1.z, a1.w};
            float b[4] = {b0.x, b0.y, b0.z, b0.w};
            #pragma unroll
            for (int i = 0; i < 8; i++)
                #pragma unroll
                for (int j = 0; j < 4; j++)
                    acc[i][j] = fmaf(a[i], b[j], acc[i][j]);
        }
        __syncthreads();
    }
    #pragma unroll
    for (int i = 0; i < 8; i++) {
        float4 o = make_float4(acc[i][0], acc[i][1], acc[i][2], acc[i][3]);
        *(float4*)&C[(m0 + tm + i) * HE + bn + tn] = o;
    }
}

// ---------------- e-pass + softmax: block per (b, dgroup of 8), 512 threads ----------------
// Thread owns t = tid&255, d-half = tid>>8 (4 d each). Double-buffered Ws tiles.
__global__ __launch_bounds__(512) void e_pass(const float* __restrict__ V,
                                              float* __restrict__ outE) {
    __shared__ float tile[2][HC][TE + 1];   // 2 x 16 x 257 floats = 32.9 KB
    __shared__ float sV[HE];                //  2 KB
    __shared__ float sU[DT * HE];           // 16 KB
    __shared__ float sE[DT][TE];            //  8 KB

    const int tid   = threadIdx.x;          // 512
    const int b     = blockIdx.x >> 4;
    const int d0    = (blockIdx.x & 15) * DT;
    const int t     = tid & (TE - 1);       // 0..255
    const int dhalf = tid >> 8;             // 0/1 -> d = dhalf*4 + 0..3

    for (int i = tid; i < HE; i += 512) sV[i] = V[i];
    for (int i = tid; i < DT * HE; i += 512)
        sU[i] = g_Uh[(b * TD + d0) * HE + i];
    const float* wsb = g_Ws + b * TE * HE;

    // prologue: load chunk 0 into buf 0
    {
        #pragma unroll
        for (int k = 0; k < 8; k++) {
            int i = tid + k * 512;              // over 256t x 16h
            int hh = i & (HC - 1), tt = i >> 4;
            tile[0][hh][tt] = wsb[tt * HE + hh];
        }
    }
    __syncthreads();

    float e_acc[4] = {};
    float pre[8];

    for (int c = 0; c < HE / HC; c++) {
        const int buf = c & 1;
        // prefetch next chunk (LDG issued before the compute phase)
        if (c + 1 < HE / HC) {
            #pragma unroll
            for (int k = 0; k < 8; k++) {
                int i = tid + k * 512;
                int hh = i & (HC - 1), tt = i >> 4;
                pre[k] = wsb[tt * HE + (c + 1) * HC + hh];
            }
        }
        // compute: MUFU-bound
        #pragma unroll
        for (int jj = 0; jj < HC; jj++) {
            float x = tile[buf][jj][t];                       // conflict-free
            float v = sV[c * HC + jj];                        // broadcast
            #pragma unroll
            for (int d = 0; d < 4; d++) {
                float u = sU[(dhalf * 4 + d) * HE + c * HC + jj];   // broadcast
                e_acc[d] = fmaf(v, fast_tanh(x + u), e_acc[d]);
            }
        }
        // stage next chunk into the other buffer
        if (c + 1 < HE / HC) {
            #pragma unroll
            for (int k = 0; k < 8; k++) {
                int i = tid + k * 512;
                int hh = i & (HC - 1), tt = i >> 4;
                tile[buf ^ 1][hh][tt] = pre[k];
            }
        }
        __syncthreads();
    }

    #pragma unroll
    for (int d = 0; d < 4; d++) sE[dhalf * 4 + d][t] = e_acc[d];
    __syncthreads();

    // softmax: warp w (0..7) handles d = w
    const int w = tid >> 5, lane = tid & 31;
    if (w < DT) {
        float vals[8];
        float m = -1e30f;
        #pragma unroll
        for (int i = 0; i < 8; i++) {
            vals[i] = sE[w][lane + 32 * i];
            m = fmaxf(m, vals[i]);
        }
        #pragma unroll
        for (int o = 16; o; o >>= 1) m = fmaxf(m, __shfl_xor_sync(0xffffffffu, m, o));
        float s = 0.f;
        #pragma unroll
        for (int i = 0; i < 8; i++) { vals[i] = __expf(vals[i] - m); s += vals[i]; }
        #pragma unroll
        for (int o = 16; o; o >>= 1) s += __shfl_xor_sync(0xffffffffu, s, o);
        float inv = 1.0f / s;
        float* oe = outE + (b * TD + d0 + w) * TE;
        #pragma unroll
        for (int i = 0; i < 8; i++) oe[lane + 32 * i] = vals[i] * inv;
    }
}

// ---------------- context: c[d,h] = sum_t e[d,t]*enc[b,t,h] ----------------
// grid (hh=2, dg=16, b=8), 256 threads: hp = tid&127 (float2 within h-half), th = tid>>7.
__global__ __launch_bounds__(256) void ctx_kernel(const float* __restrict__ enc,
                                                  const float* __restrict__ outE,
                                                  float* __restrict__ outC) {
    __shared__ float  sE[DT][TE];          // 8 KB
    __shared__ float2 red2[DT][128];       // 8 KB

    const int tid = threadIdx.x;
    const int hh = blockIdx.x;             // 0/1 h-half
    const int dg = blockIdx.y;             // 0..15
    const int b  = blockIdx.z;             // 0..7
    const int d0 = dg * DT;

    for (int i = tid; i < DT * TE; i += 256)
        ((float*)sE)[i] = outE[(b * TD + d0) * TE + i];
    __syncthreads();

    const int hp = tid & 127;
    const int th = tid >> 7;               // t-half 0/1
    const float2* enc2 = (const float2*)(enc + b * TE * HE);

    float2 acc[DT];
    #pragma unroll
    for (int d = 0; d < DT; d++) acc[d] = make_float2(0.f, 0.f);

    #pragma unroll 4
    for (int tt = 0; tt < TE / 2; tt++) {
        int t = th * (TE / 2) + tt;
        float2 v2 = enc2[t * (HE / 2) + hh * 128 + hp];   // coalesced, L2-hot
        #pragma unroll
        for (int d = 0; d < DT; d++) {
            float e = sE[d][t];                            // broadcast
            acc[d].x = fmaf(e, v2.x, acc[d].x);
            acc[d].y = fmaf(e, v2.y, acc[d].y);
        }
    }

    if (th == 1) {
        #pragma unroll
        for (int d = 0; d < DT; d++) red2[d][hp] = acc[d];
    }
    __syncthreads();
    if (th == 0) {
        #pragma unroll
        for (int d = 0; d < DT; d++) {
            float2 o = red2[d][hp];
            o.x += acc[d].x;  o.y += acc[d].y;
            ((float2*)(outC + (b * TD + d0 + d) * HE))[hh * 128 + hp] = o;
        }
    }
}

// ---------------- launch ----------------
extern "C" void kernel_launch(void* const* d_in, const int* in_sizes, int n_in,
                              void* d_out, int out_size) {
    const float* enc = (const float*)d_in[0];   // [8,256,512]
    const float* dec = (const float*)d_in[1];   // [8,128,512]
    const float* W_a = (const float*)d_in[2];   // [512,512]
    const float* U_a = (const float*)d_in[3];   // [512,512]
    const float* V_a = (const float*)d_in[4];   // [512,1]

    float* outC = (float*)d_out;                         // [8,128,512]
    float* outE = (float*)d_out + BATCH * TD * HE;       // [8,128,256]

    gemm_fused<<<dim3(HE / BN, (BATCH * TE + BATCH * TD) / BM), 128>>>(enc, dec, W_a, U_a);
    e_pass<<<BATCH * (TD / DT), 512>>>(V_a, outE);
    ctx_kernel<<<dim3(2, TD / DT, BATCH), 256>>>(enc, outE, outC);
}

// round 7
// speedup vs baseline: 1.6866x; 1.1792x over previous
#include <cuda_runtime.h>
#include <cuda_bf16.h>
#include <cstdint>

#define BATCH 8
#define TE    256
#define TD    128
#define HE    512
#define HC    16
#define DT    8

#define MROWS (BATCH * TE + BATCH * TD)   // 3072 combined A rows
#define MT_WS (BATCH * TE / 128)          // 16 m-tiles for Ws

// ---------------- scratch ----------------
__device__ float g_Ws[BATCH * TE * HE];                     // 4 MB
__device__ float g_Uh[BATCH * TD * HE];                     // 2 MB
__device__ __align__(16) __nv_bfloat16 g_Ah[MROWS * HE];    // 3 MB  A hi (enc;dec)
__device__ __align__(16) __nv_bfloat16 g_Al[MROWS * HE];    // 3 MB  A lo
__device__ __align__(16) __nv_bfloat16 g_Bh[2 * HE * HE];   // 1 MB  B hi (W^T;U^T)
__device__ __align__(16) __nv_bfloat16 g_Bl[2 * HE * HE];   // 1 MB  B lo

__device__ __forceinline__ float fast_tanh(float x) {
    float y;
    asm("tanh.approx.f32 %0, %1;" : "=f"(y) : "f"(x));
    return y;
}
__device__ __forceinline__ uint32_t smem_u32(const void* p) {
    uint32_t a;
    asm("{ .reg .u64 t; cvta.to.shared.u64 t, %1; cvt.u32.u64 %0, t; }" : "=r"(a) : "l"(p));
    return a;
}
__device__ __forceinline__ void cp16(uint32_t dst, const void* src) {
    asm volatile("cp.async.cg.shared.global [%0], [%1], 16;" :: "r"(dst), "l"(src));
}
__device__ __forceinline__ void mma_bf16(float* c, const uint32_t* a, const uint32_t* b) {
    asm volatile(
        "mma.sync.aligned.m16n8k16.row.col.f32.bf16.bf16.f32 "
        "{%0,%1,%2,%3}, {%4,%5,%6,%7}, {%8,%9}, {%0,%1,%2,%3};"
        : "+f"(c[0]), "+f"(c[1]), "+f"(c[2]), "+f"(c[3])
        : "r"(a[0]), "r"(a[1]), "r"(a[2]), "r"(a[3]), "r"(b[0]), "r"(b[1]));
}

// ================= conversion kernels =================
__global__ __launch_bounds__(512) void conv_a(const float* __restrict__ enc,
                                              const float* __restrict__ dec) {
    int i = blockIdx.x * 512 + threadIdx.x;          // over MROWS*HE/4 float4s
    int row = i / (HE / 4), q = i % (HE / 4);
    const float* src = row < BATCH * TE ? enc + row * HE
                                        : dec + (row - BATCH * TE) * HE;
    float4 v = *(const float4*)(src + 4 * q);
    float vv[4] = {v.x, v.y, v.z, v.w};
    __nv_bfloat16 h[4], l[4];
    #pragma unroll
    for (int j = 0; j < 4; j++) {
        h[j] = __float2bfloat16(vv[j]);
        l[j] = __float2bfloat16(vv[j] - __bfloat162float(h[j]));
    }
    *(uint64_t*)&g_Ah[i * 4] = *(uint64_t*)h;
    *(uint64_t*)&g_Al[i * 4] = *(uint64_t*)l;
}

// transpose + convert: g_B*[mat*512 + n][k] = split(S[k][n])
__global__ __launch_bounds__(256) void conv_b(const float* __restrict__ W,
                                              const float* __restrict__ U) {
    __shared__ float t[32][33];
    const float* S = blockIdx.z ? U : W;
    int n0 = blockIdx.x * 32, k0 = blockIdx.y * 32;
    int tx = threadIdx.x, ty = threadIdx.y;          // block (32,8)
    #pragma unroll
    for (int i = 0; i < 4; i++) {
        int r = ty + 8 * i;
        t[r][tx] = S[(k0 + r) * HE + n0 + tx];
    }
    __syncthreads();
    #pragma unroll
    for (int i = 0; i < 4; i++) {
        int n = ty + 8 * i;
        float v = t[tx][n];
        __nv_bfloat16 h = __float2bfloat16(v);
        __nv_bfloat16 l = __float2bfloat16(v - __bfloat162float(h));
        size_t o = (size_t)(blockIdx.z * HE + n0 + n) * HE + k0 + tx;
        g_Bh[o] = h;
        g_Bl[o] = l;
    }
}

// ================= HMMA GEMM (mma.sync bf16, 3-pass compensated) =================
// C tile 128x128, BK=32, 8 warps (2m x 4n), warp tile 64x32 -> 4x4 m16n8k16.
#define TILEB    (128 * 80)                  // 10240 B (80 B row stride, 64 B data)
#define STAGEB   (4 * TILEB)                 // Ah, Al, Bh, Bl
#define GEMM_SMEM (2 * STAGEB)               // 81920 B double-buffered

__global__ __launch_bounds__(256, 1) void gemm_tc() {
    extern __shared__ char smem[];
    const uint32_t sb = smem_u32(smem);
    const int tid = threadIdx.x;
    const int w = tid >> 5, lane = tid & 31;
    const int gid = lane >> 2, tig = lane & 3;
    const int mt = blockIdx.y, nt = blockIdx.x;
    const int m0 = (mt < MT_WS ? mt : mt - MT_WS) * 128;
    const int aB = (mt < MT_WS ? 0 : BATCH * TE);    // *** A-row offset: dec rows start at 2048 ***
    const int bB = (mt < MT_WS ? 0 : HE);
    float* C = (mt < MT_WS ? g_Ws : g_Uh);
    const int n0 = nt * 128;
    const int wm = (w >> 2) * 64;            // 0 / 64
    const int wn = (w & 3) * 32;             // 0..96

    // staging map: 512 cp16 per tile per chunk; row=i>>2, q=i&3
    const int s_row0 = tid >> 2, s_q = tid & 3;
    const uint32_t s_so0 = (uint32_t)(s_row0 * 80 + s_q * 16);
    const size_t s_g0 = (size_t)s_row0 * HE + s_q * 8;

    float acc[4][4][4] = {};

    auto stage = [&](int c, int s) {
        uint32_t base = sb + s * STAGEB;
        #pragma unroll
        for (int t = 0; t < 2; t++) {
            uint32_t so = s_so0 + t * 64 * 80;              // +64 rows
            size_t ga = (size_t)(aB + m0) * HE + s_g0 + (size_t)t * 64 * HE + c * 32;
            size_t gb = (size_t)(bB + n0) * HE + s_g0 + (size_t)t * 64 * HE + c * 32;
            cp16(base + 0 * TILEB + so, g_Ah + ga);
            cp16(base + 1 * TILEB + so, g_Al + ga);
            cp16(base + 2 * TILEB + so, g_Bh + gb);
            cp16(base + 3 * TILEB + so, g_Bl + gb);
        }
        asm volatile("cp.async.commit_group;" ::: "memory");
    };

    stage(0, 0);

    for (int c = 0; c < HE / 32; c++) {
        const int s = c & 1;
        if (c + 1 < HE / 32) {
            stage(c + 1, s ^ 1);
            asm volatile("cp.async.wait_group 1;" ::: "memory");
        } else {
            asm volatile("cp.async.wait_group 0;" ::: "memory");
        }
        __syncthreads();

        const char* tAh = smem + s * STAGEB + 0 * TILEB;
        const char* tAl = smem + s * STAGEB + 1 * TILEB;
        const char* tBh = smem + s * STAGEB + 2 * TILEB;
        const char* tBl = smem + s * STAGEB + 3 * TILEB;

        #pragma unroll
        for (int ks = 0; ks < 2; ks++) {
            const uint32_t kb = ks * 32 + 4 * tig;        // byte offset of k-pair in row
            uint32_t aH[4][4], aL[4][4], bH[4][2], bL[4][2];
            // A fragment: a0=(gid,klo) a1=(gid+8,klo) a2=(gid,khi) a3=(gid+8,khi)
            #pragma unroll
            for (int mi = 0; mi < 4; mi++) {
                uint32_t ra = (uint32_t)((wm + mi * 16 + gid) * 80) + kb;
                aH[mi][0] = *(const uint32_t*)(tAh + ra);
                aH[mi][1] = *(const uint32_t*)(tAh + ra + 8 * 80);
                aH[mi][2] = *(const uint32_t*)(tAh + ra + 16);
                aH[mi][3] = *(const uint32_t*)(tAh + ra + 8 * 80 + 16);
                aL[mi][0] = *(const uint32_t*)(tAl + ra);
                aL[mi][1] = *(const uint32_t*)(tAl + ra + 8 * 80);
                aL[mi][2] = *(const uint32_t*)(tAl + ra + 16);
                aL[mi][3] = *(const uint32_t*)(tAl + ra + 8 * 80 + 16);
            }
            // B fragment (col-major B[k][n] = smem row n): b0=(klo pair, n=gid), b1=(khi)
            #pragma unroll
            for (int ni = 0; ni < 4; ni++) {
                uint32_t rb = (uint32_t)((wn + ni * 8 + gid) * 80) + kb;
                bH[ni][0] = *(const uint32_t*)(tBh + rb);
                bH[ni][1] = *(const uint32_t*)(tBh + rb + 16);
                bL[ni][0] = *(const uint32_t*)(tBl + rb);
                bL[ni][1] = *(const uint32_t*)(tBl + rb + 16);
            }
            #pragma unroll
            for (int mi = 0; mi < 4; mi++)
                #pragma unroll
                for (int ni = 0; ni < 4; ni++) {
                    mma_bf16(acc[mi][ni], aH[mi], bH[ni]);
                    mma_bf16(acc[mi][ni], aL[mi], bH[ni]);
                    mma_bf16(acc[mi][ni], aH[mi], bL[ni]);
                }
        }
        __syncthreads();
    }

    // epilogue: c0,c1 -> (gid, 2tig); c2,c3 -> (gid+8, 2tig)
    const int er = gid, ec = 2 * tig;
    #pragma unroll
    for (int mi = 0; mi < 4; mi++)
        #pragma unroll
        for (int ni = 0; ni < 4; ni++) {
            int row = m0 + wm + mi * 16 + er;
            int col = n0 + wn + ni * 8 + ec;
            *(float2*)&C[(size_t)row * HE + col] =
                make_float2(acc[mi][ni][0], acc[mi][ni][1]);
            *(float2*)&C[(size_t)(row + 8) * HE + col] =
                make_float2(acc[mi][ni][2], acc[mi][ni][3]);
        }
}

// ================= e-pass + softmax (at MUFU.TANH floor) =================
__global__ __launch_bounds__(512) void e_pass(const float* __restrict__ V,
                                              float* __restrict__ outE) {
    __shared__ float tile[2][HC][TE + 1];
    __shared__ float sV[HE];
    __shared__ float sU[DT * HE];
    __shared__ float sE[DT][TE];

    const int tid   = threadIdx.x;
    const int b     = blockIdx.x >> 4;
    const int d0    = (blockIdx.x & 15) * DT;
    const int t     = tid & (TE - 1);
    const int dhalf = tid >> 8;

    for (int i = tid; i < HE; i += 512) sV[i] = V[i];
    for (int i = tid; i < DT * HE; i += 512)
        sU[i] = g_Uh[(b * TD + d0) * HE + i];
    const float* wsb = g_Ws + b * TE * HE;

    #pragma unroll
    for (int k = 0; k < 8; k++) {
        int i = tid + k * 512;
        int hh = i & (HC - 1), tt = i >> 4;
        tile[0][hh][tt] = wsb[tt * HE + hh];
    }
    __syncthreads();

    float e_acc[4] = {};
    float pre[8];

    for (int c = 0; c < HE / HC; c++) {
        const int buf = c & 1;
        if (c + 1 < HE / HC) {
            #pragma unroll
            for (int k = 0; k < 8; k++) {
                int i = tid + k * 512;
                int hh = i & (HC - 1), tt = i >> 4;
                pre[k] = wsb[tt * HE + (c + 1) * HC + hh];
            }
        }
        #pragma unroll
        for (int jj = 0; jj < HC; jj++) {
            float x = tile[buf][jj][t];
            float v = sV[c * HC + jj];
            #pragma unroll
            for (int d = 0; d < 4; d++) {
                float u = sU[(dhalf * 4 + d) * HE + c * HC + jj];
                e_acc[d] = fmaf(v, fast_tanh(x + u), e_acc[d]);
            }
        }
        if (c + 1 < HE / HC) {
            #pragma unroll
            for (int k = 0; k < 8; k++) {
                int i = tid + k * 512;
                int hh = i & (HC - 1), tt = i >> 4;
                tile[buf ^ 1][hh][tt] = pre[k];
            }
        }
        __syncthreads();
    }

    #pragma unroll
    for (int d = 0; d < 4; d++) sE[dhalf * 4 + d][t] = e_acc[d];
    __syncthreads();

    const int w = tid >> 5, lane = tid & 31;
    if (w < DT) {
        float vals[8];
        float m = -1e30f;
        #pragma unroll
        for (int i = 0; i < 8; i++) {
            vals[i] = sE[w][lane + 32 * i];
            m = fmaxf(m, vals[i]);
        }
        #pragma unroll
        for (int o = 16; o; o >>= 1) m = fmaxf(m, __shfl_xor_sync(0xffffffffu, m, o));
        float s = 0.f;
        #pragma unroll
        for (int i = 0; i < 8; i++) { vals[i] = __expf(vals[i] - m); s += vals[i]; }
        #pragma unroll
        for (int o = 16; o; o >>= 1) s += __shfl_xor_sync(0xffffffffu, s, o);
        float inv = 1.0f / s;
        float* oe = outE + (b * TD + d0 + w) * TE;
        #pragma unroll
        for (int i = 0; i < 8; i++) oe[lane + 32 * i] = vals[i] * inv;
    }
}

// ================= context =================
__global__ __launch_bounds__(256) void ctx_kernel(const float* __restrict__ enc,
                                                  const float* __restrict__ outE,
                                                  float* __restrict__ outC) {
    __shared__ float  sE[DT][TE];
    __shared__ float2 red2[DT][128];

    const int tid = threadIdx.x;
    const int hh = blockIdx.x;
    const int dg = blockIdx.y;
    const int b  = blockIdx.z;
    const int d0 = dg * DT;

    for (int i = tid; i < DT * TE; i += 256)
        ((float*)sE)[i] = outE[(b * TD + d0) * TE + i];
    __syncthreads();

    const int hp = tid & 127;
    const int th = tid >> 7;
    const float2* enc2 = (const float2*)(enc + b * TE * HE);

    float2 acc[DT];
    #pragma unroll
    for (int d = 0; d < DT; d++) acc[d] = make_float2(0.f, 0.f);

    #pragma unroll 4
    for (int tt = 0; tt < TE / 2; tt++) {
        int t = th * (TE / 2) + tt;
        float2 v2 = enc2[t * (HE / 2) + hh * 128 + hp];
        #pragma unroll
        for (int d = 0; d < DT; d++) {
            float e = sE[d][t];
            acc[d].x = fmaf(e, v2.x, acc[d].x);
            acc[d].y = fmaf(e, v2.y, acc[d].y);
        }
    }

    if (th == 1) {
        #pragma unroll
        for (int d = 0; d < DT; d++) red2[d][hp] = acc[d];
    }
    __syncthreads();
    if (th == 0) {
        #pragma unroll
        for (int d = 0; d < DT; d++) {
            float2 o = red2[d][hp];
            o.x += acc[d].x;  o.y += acc[d].y;
            ((float2*)(outC + (b * TD + d0 + d) * HE))[hh * 128 + hp] = o;
        }
    }
}

// ================= launch =================
extern "C" void kernel_launch(void* const* d_in, const int* in_sizes, int n_in,
                              void* d_out, int out_size) {
    const float* enc = (const float*)d_in[0];
    const float* dec = (const float*)d_in[1];
    const float* W_a = (const float*)d_in[2];
    const float* U_a = (const float*)d_in[3];
    const float* V_a = (const float*)d_in[4];

    float* outC = (float*)d_out;
    float* outE = (float*)d_out + BATCH * TD * HE;

    cudaFuncSetAttribute(gemm_tc, cudaFuncAttributeMaxDynamicSharedMemorySize, GEMM_SMEM);

    conv_a<<<MROWS * HE / 4 / 512, 512>>>(enc, dec);
    conv_b<<<dim3(HE / 32, HE / 32, 2), dim3(32, 8)>>>(W_a, U_a);
    gemm_tc<<<dim3(HE / 128, MROWS / 128), 256, GEMM_SMEM>>>();
    e_pass<<<BATCH * (TD / DT), 512>>>(V_a, outE);
    ctx_kernel<<<dim3(2, TD / DT, BATCH), 256>>>(enc, outE, outC);
}